// round 7
// baseline (speedup 1.0000x reference)
#include <cuda_runtime.h>
#include <cstdint>

// ============================================================================
// VectorQuantizer forward, build v7 ("pipeline" rewrite).
//
// Numerics contract (derived from rounds 1..6 evidence):
//   * reference distance bits:  d_nk = fl( fl(a_n + b_k) - 2*C_nk )
//       a_n = ||z_n||^2 (~512, so d is quantized to ulp(512)=6.1e-5),
//       b_k = ||e_k||^2, C = z.e exact-fp32-class GEMM (NOT TF32).
//   * argmin ties (identical fp32 bits) resolve to LOWEST index.
//   * a_n / b_k reduction order is argmin-irrelevant (integer-ulp in-binade
//     shifts commute with the rounding grid).
//   * C order tolerance ~1e-7: canonical ascending-k FFMA chain used.
//
// z [32768, 512] f32, emb [8192, 512] f32.
// out[0]=loss, out[1 .. 1+N*D)=z_q_st, out[1+N*D ..)=idx (as float).
// ============================================================================

namespace vq7 {

constexpr int DIM  = 512;
constexpr int KCNT = 8192;
constexpr int NTOK = 32768;

constexpr int BM = 128, BN = 128, BK = 16;
constexpr int TM = 8,   TN = 8;
constexpr int NTHR = 256;
constexpr int SPAD = 132;          // BM + 4 pad

__device__ float g_nrm[KCNT + NTOK];   // [0,KCNT): ||e_k||^2 ; [KCNT,..): ||z_n||^2
__device__ int   g_sel[NTOK];
__device__ float g_prt[NTOK];

// ----------------------------------------------------------------------------
// Fused row-norm kernel: 8 warps/block, one warp per row, covering emb then z.
// ----------------------------------------------------------------------------
__global__ void norms_fused(const float* __restrict__ emb,
                            const float* __restrict__ z) {
    const int gw   = (blockIdx.x * NTHR + threadIdx.x) >> 5;
    const int lane = threadIdx.x & 31;
    const float* src = (gw < KCNT) ? (emb + (size_t)gw * DIM)
                                   : (z + (size_t)(gw - KCNT) * DIM);
    float acc = 0.f;
    #pragma unroll
    for (int j = 0; j < DIM / 32; j++) {
        float v = src[lane + (j << 5)];
        acc = __fadd_rn(acc, __fmul_rn(v, v));
    }
    #pragma unroll
    for (int sh = 16; sh; sh >>= 1)
        acc = __fadd_rn(acc, __shfl_down_sync(0xffffffffu, acc, sh));
    if (lane == 0) g_nrm[gw] = acc;
}

// ----------------------------------------------------------------------------
// Nearest-codeword kernel: 128x128x16 tiles, 8x8 per thread, register-prefetch
// double-buffered shared pipeline. Epilogue applies the reference-rounded
// distance and a lowest-index tie-break running argmin.
// ----------------------------------------------------------------------------
__global__ __launch_bounds__(NTHR, 2)
void nearest(const float* __restrict__ z, const float* __restrict__ emb) {
    __shared__ float smA[2][BK][SPAD];
    __shared__ float smB[2][BK][SPAD];
    __shared__ float finV[BM * 16];
    __shared__ int   finI[BM * 16];

    const int tid  = threadIdx.x;
    const int cx   = tid & 15;
    const int cy   = tid >> 4;
    const int row0 = blockIdx.x * BM;

    // per-thread cooperative load coordinates (two float4 per matrix per tile)
    const int lr0 = tid >> 2;              // 0..63
    const int lr1 = lr0 + 64;              // 64..127
    const int lc  = (tid & 3) << 2;        // 0,4,8,12

    float vmin[TM];
    int   vidx[TM];
    float an[TM];
    #pragma unroll
    for (int i = 0; i < TM; i++) {
        vmin[i] = 3.4e38f; vidx[i] = 0x7fffffff;
        an[i] = g_nrm[KCNT + row0 + cy * TM + i];
    }

    for (int col0 = 0; col0 < KCNT; col0 += BN) {
        float acc[TM][TN];
        #pragma unroll
        for (int i = 0; i < TM; i++)
            #pragma unroll
            for (int j = 0; j < TN; j++) acc[i][j] = 0.f;

        float4 pa0, pa1, pb0, pb1;
        // ---- prologue: tile 0 ----
        pa0 = *reinterpret_cast<const float4*>(z   + (size_t)(row0 + lr0) * DIM + lc);
        pa1 = *reinterpret_cast<const float4*>(z   + (size_t)(row0 + lr1) * DIM + lc);
        pb0 = *reinterpret_cast<const float4*>(emb + (size_t)(col0 + lr0) * DIM + lc);
        pb1 = *reinterpret_cast<const float4*>(emb + (size_t)(col0 + lr1) * DIM + lc);
        {
            float* a0 = &smA[0][lc][lr0]; float* a1 = &smA[0][lc][lr1];
            a0[0*SPAD] = pa0.x; a0[1*SPAD] = pa0.y; a0[2*SPAD] = pa0.z; a0[3*SPAD] = pa0.w;
            a1[0*SPAD] = pa1.x; a1[1*SPAD] = pa1.y; a1[2*SPAD] = pa1.z; a1[3*SPAD] = pa1.w;
            float* b0 = &smB[0][lc][lr0]; float* b1 = &smB[0][lc][lr1];
            b0[0*SPAD] = pb0.x; b0[1*SPAD] = pb0.y; b0[2*SPAD] = pb0.z; b0[3*SPAD] = pb0.w;
            b1[0*SPAD] = pb1.x; b1[1*SPAD] = pb1.y; b1[2*SPAD] = pb1.z; b1[3*SPAD] = pb1.w;
        }
        __syncthreads();

        constexpr int NTILE = DIM / BK;    // 32
        #pragma unroll 1
        for (int t = 0; t < NTILE; t++) {
            const int cur = t & 1;
            if (t + 1 < NTILE) {
                const int kn = (t + 1) * BK;
                pa0 = *reinterpret_cast<const float4*>(z   + (size_t)(row0 + lr0) * DIM + kn + lc);
                pa1 = *reinterpret_cast<const float4*>(z   + (size_t)(row0 + lr1) * DIM + kn + lc);
                pb0 = *reinterpret_cast<const float4*>(emb + (size_t)(col0 + lr0) * DIM + kn + lc);
                pb1 = *reinterpret_cast<const float4*>(emb + (size_t)(col0 + lr1) * DIM + kn + lc);
            }
            #pragma unroll
            for (int kk = 0; kk < BK; kk++) {
                float ra[TM], rb[TN];
                #pragma unroll
                for (int i = 0; i < TM; i++) ra[i] = smA[cur][kk][cy * TM + i];
                #pragma unroll
                for (int j = 0; j < TN; j++) rb[j] = smB[cur][kk][cx * TN + j];
                #pragma unroll
                for (int i = 0; i < TM; i++)
                    #pragma unroll
                    for (int j = 0; j < TN; j++)
                        acc[i][j] = __fmaf_rn(ra[i], rb[j], acc[i][j]);
            }
            if (t + 1 < NTILE) {
                __syncthreads();
                const int nxt = (t + 1) & 1;
                float* a0 = &smA[nxt][lc][lr0]; float* a1 = &smA[nxt][lc][lr1];
                a0[0*SPAD] = pa0.x; a0[1*SPAD] = pa0.y; a0[2*SPAD] = pa0.z; a0[3*SPAD] = pa0.w;
                a1[0*SPAD] = pa1.x; a1[1*SPAD] = pa1.y; a1[2*SPAD] = pa1.z; a1[3*SPAD] = pa1.w;
                float* b0 = &smB[nxt][lc][lr0]; float* b1 = &smB[nxt][lc][lr1];
                b0[0*SPAD] = pb0.x; b0[1*SPAD] = pb0.y; b0[2*SPAD] = pb0.z; b0[3*SPAD] = pb0.w;
                b1[0*SPAD] = pb1.x; b1[1*SPAD] = pb1.y; b1[2*SPAD] = pb1.z; b1[3*SPAD] = pb1.w;
                __syncthreads();
            }
        }
        __syncthreads();

        // ---- epilogue: reference-rounded distance + running argmin ----
        #pragma unroll
        for (int j = 0; j < TN; j++) {
            const int k = col0 + cx * TN + j;
            const float bk = g_nrm[k];
            #pragma unroll
            for (int i = 0; i < TM; i++) {
                const float t = __fadd_rn(an[i], bk);            // fl(a_n + b_k)
                const float v = __fmaf_rn(-2.f, acc[i][j], t);   // fl(t - 2C)
                if (v < vmin[i] || (v == vmin[i] && k < vidx[i])) {
                    vmin[i] = v; vidx[i] = k;
                }
            }
        }
    }

    // 16-candidate cross-thread reduce per row, lowest index on ties.
    #pragma unroll
    for (int i = 0; i < TM; i++) {
        const int r = cy * TM + i;
        finV[r * 16 + cx] = vmin[i];
        finI[r * 16 + cx] = vidx[i];
    }
    __syncthreads();
    if (tid < BM) {
        float bv = finV[tid * 16];
        int   bi = finI[tid * 16];
        #pragma unroll
        for (int s = 1; s < 16; s++) {
            const float v = finV[tid * 16 + s];
            const int  ii = finI[tid * 16 + s];
            if (v < bv || (v == bv && ii < bi)) { bv = v; bi = ii; }
        }
        g_sel[row0 + tid] = bi;
    }
}

// ----------------------------------------------------------------------------
// Finalize: 2 rows per block (128 threads each): z_q_st = fl(z + fl(z_q - z)),
// per-row loss partial, idx as float.
// ----------------------------------------------------------------------------
__global__ void finalize(const float* __restrict__ z,
                         const float* __restrict__ emb,
                         float* __restrict__ out, int N) {
    const int half = threadIdx.x >> 7;              // 0 or 1
    const int lt   = threadIdx.x & 127;
    const int n    = blockIdx.x * 2 + half;
    const int k    = g_sel[n];
    const float* zr = z + (size_t)n * DIM;
    const float* er = emb + (size_t)k * DIM;
    float* o = out + 1 + (size_t)n * DIM;
    float s = 0.f;
    #pragma unroll
    for (int j = 0; j < DIM / 128; j++) {
        const int c = lt + j * 128;
        const float zv = zr[c];
        const float dx = __fadd_rn(er[c], -zv);
        o[c] = __fadd_rn(zv, dx);
        s = __fmaf_rn(dx, dx, s);
    }
    #pragma unroll
    for (int sh = 16; sh; sh >>= 1) s += __shfl_down_sync(0xffffffffu, s, sh);
    __shared__ float ws[8];
    if ((lt & 31) == 0) ws[half * 4 + (lt >> 5)] = s;
    __syncthreads();
    if (lt == 0) {
        g_prt[n] = ws[half * 4] + ws[half * 4 + 1] + ws[half * 4 + 2] + ws[half * 4 + 3];
        out[1 + (size_t)N * DIM + n] = (float)k;
    }
}

// ----------------------------------------------------------------------------
// Deterministic fixed-order loss reduce: loss = 2 * mean.
// ----------------------------------------------------------------------------
__global__ void reduce_loss(float* __restrict__ out, int N) {
    __shared__ float sm[512];
    float s = 0.f;
    for (int i = threadIdx.x; i < N; i += 512) s += g_prt[i];
    sm[threadIdx.x] = s;
    __syncthreads();
    for (int o = 256; o; o >>= 1) {
        if (threadIdx.x < o) sm[threadIdx.x] += sm[threadIdx.x + o];
        __syncthreads();
    }
    if (threadIdx.x == 0)
        out[0] = 2.f * sm[0] / ((float)N * (float)DIM);
}

}  // namespace vq7

// ----------------------------------------------------------------------------
extern "C" void kernel_launch(void* const* d_in, const int* in_sizes, int n_in,
                              void* d_out, int out_size) {
    using namespace vq7;
    const float* z   = (const float*)d_in[0];
    const float* emb = (const float*)d_in[1];
    float* out = (float*)d_out;
    const int N = in_sizes[0] / DIM;    // 32768

    norms_fused<<<(KCNT + N) / 8, NTHR>>>(emb, z);
    nearest<<<N / BM, NTHR>>>(z, emb);
    finalize<<<N / 2, NTHR>>>(z, emb, out, N);
    reduce_loss<<<1, 512>>>(out, N);
}

// round 8
// speedup vs baseline: 1.0014x; 1.0014x over previous
#include <cuda_runtime.h>
#include <cstdint>

// ============================================================================
// VectorQuantizer forward, build v7 ("pipeline" rewrite).
//
// Numerics contract (derived from rounds 1..6 evidence):
//   * reference distance bits:  d_nk = fl( fl(a_n + b_k) - 2*C_nk )
//       a_n = ||z_n||^2 (~512, so d is quantized to ulp(512)=6.1e-5),
//       b_k = ||e_k||^2, C = z.e exact-fp32-class GEMM (NOT TF32).
//   * argmin ties (identical fp32 bits) resolve to LOWEST index.
//   * a_n / b_k reduction order is argmin-irrelevant (integer-ulp in-binade
//     shifts commute with the rounding grid).
//   * C order tolerance ~1e-7: canonical ascending-k FFMA chain used.
//
// z [32768, 512] f32, emb [8192, 512] f32.
// out[0]=loss, out[1 .. 1+N*D)=z_q_st, out[1+N*D ..)=idx (as float).
// ============================================================================

namespace vq7 {

constexpr int DIM  = 512;
constexpr int KCNT = 8192;
constexpr int NTOK = 32768;

constexpr int BM = 128, BN = 128, BK = 16;
constexpr int TM = 8,   TN = 8;
constexpr int NTHR = 256;
constexpr int SPAD = 132;          // BM + 4 pad

__device__ float g_nrm[KCNT + NTOK];   // [0,KCNT): ||e_k||^2 ; [KCNT,..): ||z_n||^2
__device__ int   g_sel[NTOK];
__device__ float g_prt[NTOK];

// ----------------------------------------------------------------------------
// Fused row-norm kernel: 8 warps/block, one warp per row, covering emb then z.
// ----------------------------------------------------------------------------
__global__ void norms_fused(const float* __restrict__ emb,
                            const float* __restrict__ z) {
    const int gw   = (blockIdx.x * NTHR + threadIdx.x) >> 5;
    const int lane = threadIdx.x & 31;
    const float* src = (gw < KCNT) ? (emb + (size_t)gw * DIM)
                                   : (z + (size_t)(gw - KCNT) * DIM);
    float acc = 0.f;
    #pragma unroll
    for (int j = 0; j < DIM / 32; j++) {
        float v = src[lane + (j << 5)];
        acc = __fadd_rn(acc, __fmul_rn(v, v));
    }
    #pragma unroll
    for (int sh = 16; sh; sh >>= 1)
        acc = __fadd_rn(acc, __shfl_down_sync(0xffffffffu, acc, sh));
    if (lane == 0) g_nrm[gw] = acc;
}

// ----------------------------------------------------------------------------
// Nearest-codeword kernel: 128x128x16 tiles, 8x8 per thread, register-prefetch
// double-buffered shared pipeline. Epilogue applies the reference-rounded
// distance and a lowest-index tie-break running argmin.
// ----------------------------------------------------------------------------
__global__ __launch_bounds__(NTHR, 2)
void nearest(const float* __restrict__ z, const float* __restrict__ emb) {
    __shared__ float smA[2][BK][SPAD];
    __shared__ float smB[2][BK][SPAD];
    __shared__ float finV[BM * 16];
    __shared__ int   finI[BM * 16];

    const int tid  = threadIdx.x;
    const int cx   = tid & 15;
    const int cy   = tid >> 4;
    const int row0 = blockIdx.x * BM;

    // per-thread cooperative load coordinates (two float4 per matrix per tile)
    const int lr0 = tid >> 2;              // 0..63
    const int lr1 = lr0 + 64;              // 64..127
    const int lc  = (tid & 3) << 2;        // 0,4,8,12

    float vmin[TM];
    int   vidx[TM];
    float an[TM];
    #pragma unroll
    for (int i = 0; i < TM; i++) {
        vmin[i] = 3.4e38f; vidx[i] = 0x7fffffff;
        an[i] = g_nrm[KCNT + row0 + cy * TM + i];
    }

    for (int col0 = 0; col0 < KCNT; col0 += BN) {
        float acc[TM][TN];
        #pragma unroll
        for (int i = 0; i < TM; i++)
            #pragma unroll
            for (int j = 0; j < TN; j++) acc[i][j] = 0.f;

        float4 pa0, pa1, pb0, pb1;
        // ---- prologue: tile 0 ----
        pa0 = *reinterpret_cast<const float4*>(z   + (size_t)(row0 + lr0) * DIM + lc);
        pa1 = *reinterpret_cast<const float4*>(z   + (size_t)(row0 + lr1) * DIM + lc);
        pb0 = *reinterpret_cast<const float4*>(emb + (size_t)(col0 + lr0) * DIM + lc);
        pb1 = *reinterpret_cast<const float4*>(emb + (size_t)(col0 + lr1) * DIM + lc);
        {
            float* a0 = &smA[0][lc][lr0]; float* a1 = &smA[0][lc][lr1];
            a0[0*SPAD] = pa0.x; a0[1*SPAD] = pa0.y; a0[2*SPAD] = pa0.z; a0[3*SPAD] = pa0.w;
            a1[0*SPAD] = pa1.x; a1[1*SPAD] = pa1.y; a1[2*SPAD] = pa1.z; a1[3*SPAD] = pa1.w;
            float* b0 = &smB[0][lc][lr0]; float* b1 = &smB[0][lc][lr1];
            b0[0*SPAD] = pb0.x; b0[1*SPAD] = pb0.y; b0[2*SPAD] = pb0.z; b0[3*SPAD] = pb0.w;
            b1[0*SPAD] = pb1.x; b1[1*SPAD] = pb1.y; b1[2*SPAD] = pb1.z; b1[3*SPAD] = pb1.w;
        }
        __syncthreads();

        constexpr int NTILE = DIM / BK;    // 32
        #pragma unroll 1
        for (int t = 0; t < NTILE; t++) {
            const int cur = t & 1;
            if (t + 1 < NTILE) {
                const int kn = (t + 1) * BK;
                pa0 = *reinterpret_cast<const float4*>(z   + (size_t)(row0 + lr0) * DIM + kn + lc);
                pa1 = *reinterpret_cast<const float4*>(z   + (size_t)(row0 + lr1) * DIM + kn + lc);
                pb0 = *reinterpret_cast<const float4*>(emb + (size_t)(col0 + lr0) * DIM + kn + lc);
                pb1 = *reinterpret_cast<const float4*>(emb + (size_t)(col0 + lr1) * DIM + kn + lc);
            }
            #pragma unroll
            for (int kk = 0; kk < BK; kk++) {
                float ra[TM], rb[TN];
                #pragma unroll
                for (int i = 0; i < TM; i++) ra[i] = smA[cur][kk][cy * TM + i];
                #pragma unroll
                for (int j = 0; j < TN; j++) rb[j] = smB[cur][kk][cx * TN + j];
                #pragma unroll
                for (int i = 0; i < TM; i++)
                    #pragma unroll
                    for (int j = 0; j < TN; j++)
                        acc[i][j] = __fmaf_rn(ra[i], rb[j], acc[i][j]);
            }
            if (t + 1 < NTILE) {
                __syncthreads();
                const int nxt = (t + 1) & 1;
                float* a0 = &smA[nxt][lc][lr0]; float* a1 = &smA[nxt][lc][lr1];
                a0[0*SPAD] = pa0.x; a0[1*SPAD] = pa0.y; a0[2*SPAD] = pa0.z; a0[3*SPAD] = pa0.w;
                a1[0*SPAD] = pa1.x; a1[1*SPAD] = pa1.y; a1[2*SPAD] = pa1.z; a1[3*SPAD] = pa1.w;
                float* b0 = &smB[nxt][lc][lr0]; float* b1 = &smB[nxt][lc][lr1];
                b0[0*SPAD] = pb0.x; b0[1*SPAD] = pb0.y; b0[2*SPAD] = pb0.z; b0[3*SPAD] = pb0.w;
                b1[0*SPAD] = pb1.x; b1[1*SPAD] = pb1.y; b1[2*SPAD] = pb1.z; b1[3*SPAD] = pb1.w;
                __syncthreads();
            }
        }
        __syncthreads();

        // ---- epilogue: reference-rounded distance + running argmin ----
        #pragma unroll
        for (int j = 0; j < TN; j++) {
            const int k = col0 + cx * TN + j;
            const float bk = g_nrm[k];
            #pragma unroll
            for (int i = 0; i < TM; i++) {
                const float t = __fadd_rn(an[i], bk);            // fl(a_n + b_k)
                const float v = __fmaf_rn(-2.f, acc[i][j], t);   // fl(t - 2C)
                if (v < vmin[i] || (v == vmin[i] && k < vidx[i])) {
                    vmin[i] = v; vidx[i] = k;
                }
            }
        }
    }

    // 16-candidate cross-thread reduce per row, lowest index on ties.
    #pragma unroll
    for (int i = 0; i < TM; i++) {
        const int r = cy * TM + i;
        finV[r * 16 + cx] = vmin[i];
        finI[r * 16 + cx] = vidx[i];
    }
    __syncthreads();
    if (tid < BM) {
        float bv = finV[tid * 16];
        int   bi = finI[tid * 16];
        #pragma unroll
        for (int s = 1; s < 16; s++) {
            const float v = finV[tid * 16 + s];
            const int  ii = finI[tid * 16 + s];
            if (v < bv || (v == bv && ii < bi)) { bv = v; bi = ii; }
        }
        g_sel[row0 + tid] = bi;
    }
}

// ----------------------------------------------------------------------------
// Finalize: 2 rows per block (128 threads each): z_q_st = fl(z + fl(z_q - z)),
// per-row loss partial, idx as float.
// ----------------------------------------------------------------------------
__global__ void finalize(const float* __restrict__ z,
                         const float* __restrict__ emb,
                         float* __restrict__ out, int N) {
    const int half = threadIdx.x >> 7;              // 0 or 1
    const int lt   = threadIdx.x & 127;
    const int n    = blockIdx.x * 2 + half;
    const int k    = g_sel[n];
    const float* zr = z + (size_t)n * DIM;
    const float* er = emb + (size_t)k * DIM;
    float* o = out + 1 + (size_t)n * DIM;
    float s = 0.f;
    #pragma unroll
    for (int j = 0; j < DIM / 128; j++) {
        const int c = lt + j * 128;
        const float zv = zr[c];
        const float dx = __fadd_rn(er[c], -zv);
        o[c] = __fadd_rn(zv, dx);
        s = __fmaf_rn(dx, dx, s);
    }
    #pragma unroll
    for (int sh = 16; sh; sh >>= 1) s += __shfl_down_sync(0xffffffffu, s, sh);
    __shared__ float ws[8];
    if ((lt & 31) == 0) ws[half * 4 + (lt >> 5)] = s;
    __syncthreads();
    if (lt == 0) {
        g_prt[n] = ws[half * 4] + ws[half * 4 + 1] + ws[half * 4 + 2] + ws[half * 4 + 3];
        out[1 + (size_t)N * DIM + n] = (float)k;
    }
}

// ----------------------------------------------------------------------------
// Deterministic fixed-order loss reduce: loss = 2 * mean.
// ----------------------------------------------------------------------------
__global__ void reduce_loss(float* __restrict__ out, int N) {
    __shared__ float sm[512];
    float s = 0.f;
    for (int i = threadIdx.x; i < N; i += 512) s += g_prt[i];
    sm[threadIdx.x] = s;
    __syncthreads();
    for (int o = 256; o; o >>= 1) {
        if (threadIdx.x < o) sm[threadIdx.x] += sm[threadIdx.x + o];
        __syncthreads();
    }
    if (threadIdx.x == 0)
        out[0] = 2.f * sm[0] / ((float)N * (float)DIM);
}

}  // namespace vq7

// ----------------------------------------------------------------------------
extern "C" void kernel_launch(void* const* d_in, const int* in_sizes, int n_in,
                              void* d_out, int out_size) {
    using namespace vq7;
    const float* z   = (const float*)d_in[0];
    const float* emb = (const float*)d_in[1];
    float* out = (float*)d_out;
    const int N = in_sizes[0] / DIM;    // 32768

    norms_fused<<<(KCNT + N) / 8, NTHR>>>(emb, z);
    nearest<<<N / BM, NTHR>>>(z, emb);
    finalize<<<N / 2, NTHR>>>(z, emb, out, N);
    reduce_loss<<<1, 512>>>(out, N);
}

// round 10
// speedup vs baseline: 2.1985x; 2.1953x over previous
#include <cuda_runtime.h>
#include <cuda_bf16.h>
#include <mma.h>
#include <cstdint>

// ============================================================================
// VQ forward v10: wmma bf16 (HMMA, baseline ISA - no tcgen05 on this
// toolchain) approx GEMM -> margin candidate filter -> exact fp32 rescore.
// Exact-bits contract (validated R7): d = fl(fl(a_n+b_k) - 2C), C computed
// as ascending-k single-accumulator FFMA chain, ties -> lowest index.
// ============================================================================

namespace vq10 {
using namespace nvcuda;

constexpr int DIM  = 512;
constexpr int KCNT = 8192;
constexpr int NTOK = 32768;
constexpr int BM   = 128;
constexpr int BN   = 128;
constexpr int CAP  = 256;
constexpr float MARGIN = 0.032f;   // >= 2*bf16 dot bound (0.0107) + quantum

constexpr int LDA = 520;           // bf16 elems (512 + 8 pad)
constexpr int LDB = 40;            // bf16 elems (32 + 8 pad)
constexpr int LDC = 136;           // f32 elems (128 + 8 pad)
constexpr int BUF = 128 * LDB;     // bf16 elems per B stage buffer
constexpr int SM_AS = 0;                         // 128*520*2   = 133120 B
constexpr int SM_BS = SM_AS + 128 * LDA * 2;     // 2*128*40*2  =  20480 B
constexpr int SM_CS = SM_BS + 2 * BUF * 2;       // 128*136*4   =  69632 B
constexpr int SM_TOT = SM_CS + 128 * LDC * 4;    // total 223232 B

__device__ float g_nrm[KCNT + NTOK];   // [0,KCNT): ||e||^2 ; rest: ||z||^2
__device__ int   g_sel[NTOK];
__device__ float g_prt[NTOK];
__device__ __nv_bfloat16 g_embh[KCNT * DIM];
__device__ int   g_cnt[NTOK];
__device__ int   g_cand[(size_t)NTOK * CAP];

// ---------------------------------------------------------------------------
// Exact fp32 row norms (R7, passed). Order is argmin-irrelevant.
// ---------------------------------------------------------------------------
__global__ void norms_fused(const float* __restrict__ emb,
                            const float* __restrict__ z) {
    const int gw = (blockIdx.x * 256 + threadIdx.x) >> 5;
    const int lane = threadIdx.x & 31;
    const float* src = (gw < KCNT) ? (emb + (size_t)gw * DIM)
                                   : (z + (size_t)(gw - KCNT) * DIM);
    float acc = 0.f;
    #pragma unroll
    for (int j = 0; j < DIM / 32; j++) {
        float v = src[lane + (j << 5)];
        acc = __fadd_rn(acc, __fmul_rn(v, v));
    }
    #pragma unroll
    for (int sh = 16; sh; sh >>= 1)
        acc = __fadd_rn(acc, __shfl_down_sync(0xffffffffu, acc, sh));
    if (lane == 0) g_nrm[gw] = acc;
}

// emb fp32 -> bf16 (rn) codebook copy.
__global__ void prep(const float* __restrict__ emb) {
    const int i = blockIdx.x * 256 + threadIdx.x;   // [0, 1048576)
    float4 v = reinterpret_cast<const float4*>(emb)[i];
    reinterpret_cast<__nv_bfloat162*>(g_embh)[2*i]   = __floats2bfloat162_rn(v.x, v.y);
    reinterpret_cast<__nv_bfloat162*>(g_embh)[2*i+1] = __floats2bfloat162_rn(v.z, v.w);
}

// ---------------------------------------------------------------------------
// Approx pass: wmma bf16. CTA = 128 z rows resident in smem (bf16).
// 8 warps (4 m-groups x 2 n-groups), warp tile 32x64, K chunked by 32 with
// double-buffered B staging from the bf16 codebook. Per col-tile the fp32 C
// block goes to smem; one thread per row keeps a running max and pushes
// margin candidates (no atomics - single writer per row).
// ---------------------------------------------------------------------------
__global__ __launch_bounds__(256, 1)
void tc_pass(const float* __restrict__ z) {
    extern __shared__ char smraw[];
    __nv_bfloat16* As = reinterpret_cast<__nv_bfloat16*>(smraw + SM_AS);
    __nv_bfloat16* Bs = reinterpret_cast<__nv_bfloat16*>(smraw + SM_BS);
    float*         Cs = reinterpret_cast<float*>(smraw + SM_CS);

    const int tid = threadIdx.x;
    const int wid = tid >> 5;
    const int wm  = wid & 3;          // 4 row groups of 32
    const int wn  = wid >> 2;         // 2 col groups of 64
    const int row0 = blockIdx.x * BM;

    // Stage A: z rows -> bf16 row-major [128][LDA].
    for (int i = tid; i < 128 * 256; i += 256) {
        const int r = i >> 8, c2 = i & 255;
        float2 f = *reinterpret_cast<const float2*>(z + (size_t)(row0 + r) * DIM + 2 * c2);
        *reinterpret_cast<__nv_bfloat162*>(As + r * LDA + 2 * c2) =
            __floats2bfloat162_rn(f.x, f.y);
    }
    __syncthreads();

    float runmax = -3.4e38f;
    int   ccnt   = 0;

    const uint4* eb = reinterpret_cast<const uint4*>(g_embh);  // row = 64 uint4

    for (int ct = 0; ct < KCNT / BN; ct++) {
        const int col0 = ct * BN;

        wmma::fragment<wmma::accumulator, 16, 16, 16, float> acc[2][4];
        #pragma unroll
        for (int i = 0; i < 2; i++)
            #pragma unroll
            for (int j = 0; j < 4; j++) wmma::fill_fragment(acc[i][j], 0.0f);

        // stage k-chunk 0 -> buffer 0   (128 rows x 32 k = 4 uint4/row)
        for (int i = tid; i < 512; i += 256) {
            const int r = i >> 2, p = i & 3;
            *reinterpret_cast<uint4*>(Bs + r * LDB + p * 8) =
                eb[(size_t)(col0 + r) * 64 + p];
        }
        __syncthreads();

        #pragma unroll 1
        for (int kc = 0; kc < DIM / 32; kc++) {
            const int cur = kc & 1;
            if (kc < DIM / 32 - 1) {   // stage next chunk into other buffer
                __nv_bfloat16* dst = Bs + (cur ^ 1) * BUF;
                const int ko = (kc + 1) * 4;
                for (int i = tid; i < 512; i += 256) {
                    const int r = i >> 2, p = i & 3;
                    *reinterpret_cast<uint4*>(dst + r * LDB + p * 8) =
                        eb[(size_t)(col0 + r) * 64 + ko + p];
                }
            }
            const __nv_bfloat16* bb = Bs + cur * BUF;
            #pragma unroll
            for (int ks = 0; ks < 2; ks++) {
                wmma::fragment<wmma::matrix_a, 16, 16, 16, __nv_bfloat16, wmma::row_major> af[2];
                wmma::fragment<wmma::matrix_b, 16, 16, 16, __nv_bfloat16, wmma::col_major> bf[4];
                #pragma unroll
                for (int i = 0; i < 2; i++)
                    wmma::load_matrix_sync(af[i],
                        As + (wm * 32 + i * 16) * LDA + kc * 32 + ks * 16, LDA);
                #pragma unroll
                for (int j = 0; j < 4; j++)
                    wmma::load_matrix_sync(bf[j],
                        bb + (wn * 64 + j * 16) * LDB + ks * 16, LDB);
                #pragma unroll
                for (int i = 0; i < 2; i++)
                    #pragma unroll
                    for (int j = 0; j < 4; j++)
                        wmma::mma_sync(acc[i][j], af[i], bf[j], acc[i][j]);
            }
            __syncthreads();
        }

        // C block -> smem
        #pragma unroll
        for (int i = 0; i < 2; i++)
            #pragma unroll
            for (int j = 0; j < 4; j++)
                wmma::store_matrix_sync(
                    Cs + (wm * 32 + i * 16) * LDC + wn * 64 + j * 16,
                    acc[i][j], LDC, wmma::mem_row_major);
        __syncthreads();

        // Per-row running max + margin candidates (thread tid owns row tid).
        if (tid < 128) {
            const float4* cr = reinterpret_cast<const float4*>(Cs + tid * LDC);
            float mx = runmax;
            #pragma unroll
            for (int q = 0; q < 32; q++) {
                const float4 v = cr[q];
                mx = fmaxf(mx, fmaxf(fmaxf(v.x, v.y), fmaxf(v.z, v.w)));
            }
            runmax = mx;
            const float thr = mx - MARGIN;
            const int rowG = row0 + tid;
            #pragma unroll
            for (int q = 0; q < 32; q++) {
                const float4 v = cr[q];
                const int kb = col0 + 4 * q;
                if (v.x >= thr) { if (ccnt < CAP) g_cand[(size_t)rowG * CAP + ccnt] = kb;     ccnt++; }
                if (v.y >= thr) { if (ccnt < CAP) g_cand[(size_t)rowG * CAP + ccnt] = kb + 1; ccnt++; }
                if (v.z >= thr) { if (ccnt < CAP) g_cand[(size_t)rowG * CAP + ccnt] = kb + 2; ccnt++; }
                if (v.w >= thr) { if (ccnt < CAP) g_cand[(size_t)rowG * CAP + ccnt] = kb + 3; ccnt++; }
            }
        }
        __syncthreads();
    }
    if (tid < 128) g_cnt[row0 + tid] = ccnt;
}

// ---------------------------------------------------------------------------
// Exact rescore: one thread per row. C = ascending-k single-accumulator fp32
// FFMA chain (identical to R7), v = fl(fl(a_n+b_k) - 2C), lex-min (v, k).
// Full-scan fallback if the candidate list overflowed (never expected).
// ---------------------------------------------------------------------------
__global__ void rescore(const float* __restrict__ z, const float* __restrict__ emb) {
    const int n = blockIdx.x * 256 + threadIdx.x;
    if (n >= NTOK) return;
    const float an = g_nrm[KCNT + n];
    const float4* zr = reinterpret_cast<const float4*>(z + (size_t)n * DIM);
    int cnt = g_cnt[n];
    const bool overflow = (cnt > CAP);
    if (overflow) cnt = KCNT;
    float bv = 3.4e38f;
    int   bi = 0x7fffffff;
    for (int s = 0; s < cnt; s++) {
        const int k = overflow ? s : g_cand[(size_t)n * CAP + s];
        const float4* er = reinterpret_cast<const float4*>(emb + (size_t)k * DIM);
        float acc = 0.f;
        #pragma unroll 4
        for (int q = 0; q < DIM / 4; q++) {
            const float4 a = zr[q], b = er[q];
            acc = __fmaf_rn(a.x, b.x, acc);
            acc = __fmaf_rn(a.y, b.y, acc);
            acc = __fmaf_rn(a.z, b.z, acc);
            acc = __fmaf_rn(a.w, b.w, acc);
        }
        const float t = __fadd_rn(an, g_nrm[k]);
        const float v = __fmaf_rn(-2.f, acc, t);
        if (v < bv || (v == bv && k < bi)) { bv = v; bi = k; }
    }
    g_sel[n] = bi;
}

// ---------------------------------------------------------------------------
__global__ void finalize(const float* __restrict__ z, const float* __restrict__ emb,
                         float* __restrict__ out, int N) {
    const int half = threadIdx.x >> 7;
    const int lt   = threadIdx.x & 127;
    const int n    = blockIdx.x * 2 + half;
    const int k    = g_sel[n];
    const float* zr = z + (size_t)n * DIM;
    const float* er = emb + (size_t)k * DIM;
    float* o = out + 1 + (size_t)n * DIM;
    float s = 0.f;
    #pragma unroll
    for (int j = 0; j < DIM / 128; j++) {
        const int c = lt + j * 128;
        const float zv = zr[c];
        const float dx = __fadd_rn(er[c], -zv);
        o[c] = __fadd_rn(zv, dx);
        s = __fmaf_rn(dx, dx, s);
    }
    #pragma unroll
    for (int sh = 16; sh; sh >>= 1) s += __shfl_down_sync(0xffffffffu, s, sh);
    __shared__ float ws[8];
    if ((lt & 31) == 0) ws[half * 4 + (lt >> 5)] = s;
    __syncthreads();
    if (lt == 0) {
        g_prt[n] = ws[half*4] + ws[half*4+1] + ws[half*4+2] + ws[half*4+3];
        out[1 + (size_t)N * DIM + n] = (float)k;
    }
}

__global__ void reduce_loss(float* __restrict__ out, int N) {
    __shared__ float sm[512];
    float s = 0.f;
    for (int i = threadIdx.x; i < N; i += 512) s += g_prt[i];
    sm[threadIdx.x] = s;
    __syncthreads();
    for (int o = 256; o; o >>= 1) {
        if (threadIdx.x < o) sm[threadIdx.x] += sm[threadIdx.x + o];
        __syncthreads();
    }
    if (threadIdx.x == 0) out[0] = 2.f * sm[0] / ((float)N * (float)DIM);
}

}  // namespace vq10

// ----------------------------------------------------------------------------
extern "C" void kernel_launch(void* const* d_in, const int* in_sizes, int n_in,
                              void* d_out, int out_size) {
    using namespace vq10;
    const float* z   = (const float*)d_in[0];
    const float* emb = (const float*)d_in[1];
    float* out = (float*)d_out;
    const int N = in_sizes[0] / DIM;    // 32768

    cudaFuncSetAttribute(tc_pass, cudaFuncAttributeMaxDynamicSharedMemorySize, SM_TOT);

    norms_fused<<<(KCNT + N) / 8, 256>>>(emb, z);
    prep<<<KCNT * DIM / 4 / 256, 256>>>(emb);
    tc_pass<<<N / BM, 256, SM_TOT>>>(z);
    rescore<<<N / 256, 256>>>(z, emb);
    finalize<<<N / 2, 256>>>(z, emb, out, N);
    reduce_loss<<<1, 512>>>(out, N);
}

// round 11
// speedup vs baseline: 3.3791x; 1.5370x over previous
#include <cuda_runtime.h>
#include <cuda_bf16.h>
#include <mma.h>
#include <cstdint>

// ============================================================================
// VQ forward v11: wmma bf16 approx GEMM (cp.async pipelined) -> margin filter
// (with stored approx scores for pruning) -> exact fp32 warp-parallel rescore.
// Exact-bits contract (validated R7/R10): d = fl(fl(a_n+b_k) - 2C), C =
// ascending-k single-accumulator fp32 FFMA chain, ties -> lowest index.
// ============================================================================

namespace vq11 {
using namespace nvcuda;

constexpr int DIM  = 512;
constexpr int KCNT = 8192;
constexpr int NTOK = 32768;
constexpr int BM   = 128;
constexpr int BN   = 128;
constexpr int CAP  = 256;
constexpr float MARGIN = 0.032f;   // >= 2*bf16 dot bound (0.0107) + quantum

constexpr int LDA = 520;           // bf16 elems (512 + 8 pad)
constexpr int LDB = 40;            // bf16 elems (32 + 8 pad)
constexpr int LDC = 136;           // f32 elems (128 + 8 pad)
constexpr int BUF = 128 * LDB;     // bf16 elems per B stage buffer
constexpr int SM_AS = 0;                         // 128*520*2   = 133120 B
constexpr int SM_BS = SM_AS + 128 * LDA * 2;     // 2*128*40*2  =  20480 B
constexpr int SM_CS = SM_BS + 2 * BUF * 2;       // 128*136*4   =  69632 B
constexpr int SM_TOT = SM_CS + 128 * LDC * 4;    // 223232 B

__device__ float g_nrm[KCNT + NTOK];   // [0,KCNT): ||e||^2 ; rest: ||z||^2
__device__ int   g_sel[NTOK];
__device__ float g_prt[NTOK];
__device__ __nv_bfloat16 g_embh[KCNT * DIM];
__device__ int   g_cnt[NTOK];
__device__ int   g_cand[(size_t)NTOK * CAP];
__device__ float g_cval[(size_t)NTOK * CAP];

// ----------------- cp.async helpers (baseline ISA, sm_80+) -----------------
__device__ __forceinline__ void cp_async16(void* dst_smem, const void* src) {
    uint32_t d = (uint32_t)__cvta_generic_to_shared(dst_smem);
    asm volatile("cp.async.ca.shared.global [%0], [%1], 16;" :: "r"(d), "l"(src));
}
__device__ __forceinline__ void cp_commit() {
    asm volatile("cp.async.commit_group;" ::: "memory");
}
template <int N>
__device__ __forceinline__ void cp_wait() {
    asm volatile("cp.async.wait_group %0;" :: "n"(N) : "memory");
}

// ---------------------------------------------------------------------------
// Exact fp32 row norms (validated). Order is argmin-irrelevant.
// ---------------------------------------------------------------------------
__global__ void norms_fused(const float* __restrict__ emb,
                            const float* __restrict__ z) {
    const int gw = (blockIdx.x * 256 + threadIdx.x) >> 5;
    const int lane = threadIdx.x & 31;
    const float* src = (gw < KCNT) ? (emb + (size_t)gw * DIM)
                                   : (z + (size_t)(gw - KCNT) * DIM);
    float acc = 0.f;
    #pragma unroll
    for (int j = 0; j < DIM / 32; j++) {
        float v = src[lane + (j << 5)];
        acc = __fadd_rn(acc, __fmul_rn(v, v));
    }
    #pragma unroll
    for (int sh = 16; sh; sh >>= 1)
        acc = __fadd_rn(acc, __shfl_down_sync(0xffffffffu, acc, sh));
    if (lane == 0) g_nrm[gw] = acc;
}

// emb fp32 -> bf16 (rn) codebook copy.
__global__ void prep(const float* __restrict__ emb) {
    const int i = blockIdx.x * 256 + threadIdx.x;   // [0, 1048576)
    float4 v = reinterpret_cast<const float4*>(emb)[i];
    reinterpret_cast<__nv_bfloat162*>(g_embh)[2*i]   = __floats2bfloat162_rn(v.x, v.y);
    reinterpret_cast<__nv_bfloat162*>(g_embh)[2*i+1] = __floats2bfloat162_rn(v.z, v.w);
}

// ---------------------------------------------------------------------------
// Approx pass: wmma bf16, CTA = 128 z rows resident. 8 warps (4m x 2n),
// warp tile 32x64, K chunked by 32 with cp.async 2-stage B pipeline.
// Per col-tile: C -> smem, per-row running max + margin candidate push
// (single writer per row; stores approx score for later pruning).
// ---------------------------------------------------------------------------
__global__ __launch_bounds__(256, 1)
void tc_pass(const float* __restrict__ z) {
    extern __shared__ char smraw[];
    __nv_bfloat16* As = reinterpret_cast<__nv_bfloat16*>(smraw + SM_AS);
    __nv_bfloat16* Bs = reinterpret_cast<__nv_bfloat16*>(smraw + SM_BS);
    float*         Cs = reinterpret_cast<float*>(smraw + SM_CS);

    const int tid = threadIdx.x;
    const int wid = tid >> 5;
    const int wm  = wid & 3;
    const int wn  = wid >> 2;
    const int row0 = blockIdx.x * BM;

    // Stage A: z rows -> bf16 row-major [128][LDA].
    for (int i = tid; i < 128 * 256; i += 256) {
        const int r = i >> 8, c2 = i & 255;
        float2 f = *reinterpret_cast<const float2*>(z + (size_t)(row0 + r) * DIM + 2 * c2);
        *reinterpret_cast<__nv_bfloat162*>(As + r * LDA + 2 * c2) =
            __floats2bfloat162_rn(f.x, f.y);
    }
    __syncthreads();

    float runmax = -3.4e38f;
    int   ccnt   = 0;
    const uint4* eb = reinterpret_cast<const uint4*>(g_embh);  // row = 64 uint4

    for (int ct = 0; ct < KCNT / BN; ct++) {
        const int col0 = ct * BN;

        wmma::fragment<wmma::accumulator, 16, 16, 16, float> acc[2][4];
        #pragma unroll
        for (int i = 0; i < 2; i++)
            #pragma unroll
            for (int j = 0; j < 4; j++) wmma::fill_fragment(acc[i][j], 0.0f);

        // prologue: k-chunk 0 -> buffer 0 (512 x 16B, 2 per thread)
        #pragma unroll
        for (int i = tid; i < 512; i += 256) {
            const int r = i >> 2, p = i & 3;
            cp_async16(Bs + r * LDB + p * 8, &eb[(size_t)(col0 + r) * 64 + p]);
        }
        cp_commit();

        #pragma unroll 1
        for (int kc = 0; kc < DIM / 32; kc++) {
            const int cur = kc & 1;
            if (kc + 1 < DIM / 32) {   // stage next chunk into other buffer
                __nv_bfloat16* dst = Bs + (cur ^ 1) * BUF;
                const int ko = (kc + 1) * 4;
                #pragma unroll
                for (int i = tid; i < 512; i += 256) {
                    const int r = i >> 2, p = i & 3;
                    cp_async16(dst + r * LDB + p * 8,
                               &eb[(size_t)(col0 + r) * 64 + ko + p]);
                }
                cp_commit();
                cp_wait<1>();          // chunk kc resident
            } else {
                cp_wait<0>();
            }
            __syncthreads();

            const __nv_bfloat16* bb = Bs + cur * BUF;
            #pragma unroll
            for (int ks = 0; ks < 2; ks++) {
                wmma::fragment<wmma::matrix_a, 16, 16, 16, __nv_bfloat16, wmma::row_major> af[2];
                wmma::fragment<wmma::matrix_b, 16, 16, 16, __nv_bfloat16, wmma::col_major> bf[4];
                #pragma unroll
                for (int i = 0; i < 2; i++)
                    wmma::load_matrix_sync(af[i],
                        As + (wm * 32 + i * 16) * LDA + kc * 32 + ks * 16, LDA);
                #pragma unroll
                for (int j = 0; j < 4; j++)
                    wmma::load_matrix_sync(bf[j],
                        bb + (wn * 64 + j * 16) * LDB + ks * 16, LDB);
                #pragma unroll
                for (int i = 0; i < 2; i++)
                    #pragma unroll
                    for (int j = 0; j < 4; j++)
                        wmma::mma_sync(acc[i][j], af[i], bf[j], acc[i][j]);
            }
            __syncthreads();           // buf cur consumed; reusable at kc+2
        }

        // C block -> smem
        #pragma unroll
        for (int i = 0; i < 2; i++)
            #pragma unroll
            for (int j = 0; j < 4; j++)
                wmma::store_matrix_sync(
                    Cs + (wm * 32 + i * 16) * LDC + wn * 64 + j * 16,
                    acc[i][j], LDC, wmma::mem_row_major);
        __syncthreads();

        // Per-row running max + margin candidate push (+approx score).
        if (tid < 128) {
            const float4* cr = reinterpret_cast<const float4*>(Cs + tid * LDC);
            float mx = runmax;
            #pragma unroll
            for (int q = 0; q < 32; q++) {
                const float4 v = cr[q];
                mx = fmaxf(mx, fmaxf(fmaxf(v.x, v.y), fmaxf(v.z, v.w)));
            }
            runmax = mx;
            const float thr = mx - MARGIN;
            const int rowG = row0 + tid;
            const size_t base = (size_t)rowG * CAP;
            #pragma unroll
            for (int q = 0; q < 32; q++) {
                const float4 v = cr[q];
                const int kb = col0 + 4 * q;
                if (v.x >= thr) { if (ccnt < CAP) { g_cand[base+ccnt]=kb;   g_cval[base+ccnt]=v.x; } ccnt++; }
                if (v.y >= thr) { if (ccnt < CAP) { g_cand[base+ccnt]=kb+1; g_cval[base+ccnt]=v.y; } ccnt++; }
                if (v.z >= thr) { if (ccnt < CAP) { g_cand[base+ccnt]=kb+2; g_cval[base+ccnt]=v.z; } ccnt++; }
                if (v.w >= thr) { if (ccnt < CAP) { g_cand[base+ccnt]=kb+3; g_cval[base+ccnt]=v.w; } ccnt++; }
            }
        }
        __syncthreads();
    }
    if (tid < 128) g_cnt[row0 + tid] = ccnt;
}

// ---------------------------------------------------------------------------
// Exact rescore: one WARP per row, one candidate per lane. Each lane runs the
// identical ascending-k single-accumulator fp32 FFMA chain for its candidate;
// v = fl(fl(a_n+b_k) - 2C); warp lex-min (v, k). Candidates first pruned
// against the row's global approx max (provable margin). Full-scan fallback
// on counter overflow (not expected).
// ---------------------------------------------------------------------------
__device__ __forceinline__ void exact_score(const float4* __restrict__ zr,
                                            const float* __restrict__ emb,
                                            float an, int k,
                                            float& bv, int& bi) {
    const float4* er = reinterpret_cast<const float4*>(emb + (size_t)k * DIM);
    float acc = 0.f;
    #pragma unroll 8
    for (int q = 0; q < DIM / 4; q++) {
        const float4 a = zr[q], b = er[q];
        acc = __fmaf_rn(a.x, b.x, acc);
        acc = __fmaf_rn(a.y, b.y, acc);
        acc = __fmaf_rn(a.z, b.z, acc);
        acc = __fmaf_rn(a.w, b.w, acc);
    }
    const float t = __fadd_rn(an, g_nrm[k]);
    const float v = __fmaf_rn(-2.f, acc, t);
    if (v < bv || (v == bv && k < bi)) { bv = v; bi = k; }
}

__global__ void rescore(const float* __restrict__ z, const float* __restrict__ emb) {
    const int n    = (blockIdx.x * 256 + threadIdx.x) >> 5;   // row (warp id)
    const int lane = threadIdx.x & 31;
    if (n >= NTOK) return;
    const float an = g_nrm[KCNT + n];
    const float4* zr = reinterpret_cast<const float4*>(z + (size_t)n * DIM);
    const int cnt = g_cnt[n];
    float bv = 3.4e38f;
    int   bi = 0x7fffffff;

    if (cnt > CAP) {                    // fallback: exact full scan
        for (int k = lane; k < KCNT; k += 32)
            exact_score(zr, emb, an, k, bv, bi);
    } else {
        const size_t base = (size_t)n * CAP;
        float cmax = -3.4e38f;
        for (int s = lane; s < cnt; s += 32) cmax = fmaxf(cmax, g_cval[base + s]);
        #pragma unroll
        for (int o = 16; o; o >>= 1)
            cmax = fmaxf(cmax, __shfl_xor_sync(0xffffffffu, cmax, o));
        const float thr = cmax - MARGIN;
        for (int s = lane; s < cnt; s += 32) {
            if (g_cval[base + s] < thr) continue;
            exact_score(zr, emb, an, g_cand[base + s], bv, bi);
        }
    }
    #pragma unroll
    for (int o = 16; o; o >>= 1) {
        const float v2 = __shfl_xor_sync(0xffffffffu, bv, o);
        const int   i2 = __shfl_xor_sync(0xffffffffu, bi, o);
        if (v2 < bv || (v2 == bv && i2 < bi)) { bv = v2; bi = i2; }
    }
    if (lane == 0) g_sel[n] = bi;
}

// ---------------------------------------------------------------------------
__global__ void finalize(const float* __restrict__ z, const float* __restrict__ emb,
                         float* __restrict__ out, int N) {
    const int half = threadIdx.x >> 7;
    const int lt   = threadIdx.x & 127;
    const int n    = blockIdx.x * 2 + half;
    const int k    = g_sel[n];
    const float* zr = z + (size_t)n * DIM;
    const float* er = emb + (size_t)k * DIM;
    float* o = out + 1 + (size_t)n * DIM;
    float s = 0.f;
    #pragma unroll
    for (int j = 0; j < DIM / 128; j++) {
        const int c = lt + j * 128;
        const float zv = zr[c];
        const float dx = __fadd_rn(er[c], -zv);
        o[c] = __fadd_rn(zv, dx);
        s = __fmaf_rn(dx, dx, s);
    }
    #pragma unroll
    for (int sh = 16; sh; sh >>= 1) s += __shfl_down_sync(0xffffffffu, s, sh);
    __shared__ float ws[8];
    if ((lt & 31) == 0) ws[half * 4 + (lt >> 5)] = s;
    __syncthreads();
    if (lt == 0) {
        g_prt[n] = ws[half*4] + ws[half*4+1] + ws[half*4+2] + ws[half*4+3];
        out[1 + (size_t)N * DIM + n] = (float)k;
    }
}

__global__ void reduce_loss(float* __restrict__ out, int N) {
    __shared__ float sm[512];
    float s = 0.f;
    for (int i = threadIdx.x; i < N; i += 512) s += g_prt[i];
    sm[threadIdx.x] = s;
    __syncthreads();
    for (int o = 256; o; o >>= 1) {
        if (threadIdx.x < o) sm[threadIdx.x] += sm[threadIdx.x + o];
        __syncthreads();
    }
    if (threadIdx.x == 0) out[0] = 2.f * sm[0] / ((float)N * (float)DIM);
}

}  // namespace vq11

// ----------------------------------------------------------------------------
extern "C" void kernel_launch(void* const* d_in, const int* in_sizes, int n_in,
                              void* d_out, int out_size) {
    using namespace vq11;
    const float* z   = (const float*)d_in[0];
    const float* emb = (const float*)d_in[1];
    float* out = (float*)d_out;
    const int N = in_sizes[0] / DIM;    // 32768

    cudaFuncSetAttribute(tc_pass, cudaFuncAttributeMaxDynamicSharedMemorySize, SM_TOT);

    norms_fused<<<(KCNT + N) / 8, 256>>>(emb, z);
    prep<<<KCNT * DIM / 4 / 256, 256>>>(emb);
    tc_pass<<<N / BM, 256, SM_TOT>>>(z);
    rescore<<<N * 32 / 256, 256>>>(z, emb);
    finalize<<<N / 2, 256>>>(z, emb, out, N);
    reduce_loss<<<1, 512>>>(out, N);
}